// round 1
// baseline (speedup 1.0000x reference)
#include <cuda_runtime.h>
#include <cuda_bf16.h>
#include <cstdint>

// Problem shape (fixed by the reference):
//   Z: [16, 4096, 64] f32, A: [4096, 4096] f32, W: [64, 64] f32
//   out[b,n,e] = sum_m A[n,m] * (sum_d Z[b,m,d] * W[d,e])
// Restructured: X[m, b*64+e] = (Z@W); Y = A @ X  (single 4096x4096x1024 GEMM)

#define B_   16
#define N_   4096
#define D_   64
#define NCOL 1024   // B_*D_

// 16 MB scratch for X[m, b*64+e] — device global (no allocations allowed)
__device__ float g_X[(size_t)N_ * NCOL];

// ---------------------------------------------------------------------------
// Stage 1: X[m, b*64+e] = sum_d Z[b,m,d] * W[d,e]
// One block = 16 flattened rows (r = b*4096+m). 256 threads.
// ---------------------------------------------------------------------------
__global__ __launch_bounds__(256) void zw_kernel(const float* __restrict__ Z,
                                                 const float* __restrict__ W) {
    __shared__ float sW[D_ * D_];     // 16 KB
    __shared__ float sZ[16 * D_];     // 4 KB

    const int tid = threadIdx.x;

    // Load W (64x64) into smem
    #pragma unroll
    for (int i = tid; i < D_ * D_; i += 256) sW[i] = W[i];

    // Load 16 Z rows (1024 floats) via float4 — fully coalesced
    const int r0 = blockIdx.x * 16;
    const float4* Zblk = reinterpret_cast<const float4*>(Z + (size_t)r0 * D_);
    reinterpret_cast<float4*>(sZ)[tid] = Zblk[tid];
    __syncthreads();

    const int rl = tid >> 4;          // local row 0..15
    const int c0 = (tid & 15) * 4;    // output col group 0..60

    float4 acc = make_float4(0.f, 0.f, 0.f, 0.f);
    #pragma unroll
    for (int d = 0; d < D_; d++) {
        const float z = sZ[rl * D_ + d];
        const float4 w = *reinterpret_cast<const float4*>(&sW[d * D_ + c0]);
        acc.x += z * w.x; acc.y += z * w.y; acc.z += z * w.z; acc.w += z * w.w;
    }

    const int r = r0 + rl;            // r = b*4096 + m
    const int b = r >> 12;
    const int m = r & (N_ - 1);
    *reinterpret_cast<float4*>(g_X + (size_t)m * NCOL + b * D_ + c0) = acc;
}

// ---------------------------------------------------------------------------
// Stage 2: Y[n, col] = sum_m A[n,m] * X[m, col], scattered to out[b,n,e]
// Classic 128x128x8 register-tiled SGEMM, 256 threads, 8x8 microtile.
// ---------------------------------------------------------------------------
#define BM 128
#define BN 128
#define BK 8
#define TM 8
#define TN 8

__global__ __launch_bounds__(256) void gemm_ax_kernel(const float* __restrict__ A,
                                                      float* __restrict__ out) {
    __shared__ float As[BK][BM];   // A tile transposed: As[k][m]
    __shared__ float Bs[BK][BN];

    const int tid = threadIdx.x;
    const int blockRow = blockIdx.y;      // n-tile: 0..31
    const int blockCol = blockIdx.x;      // col-tile: 0..7

    const float* Aptr = A + (size_t)blockRow * BM * N_;
    const float* Bptr = g_X + blockCol * BN;

    // A-tile load mapping (128x8 floats, one float4/thread)
    const int aRow = tid >> 1;            // 0..127
    const int aCol = (tid & 1) * 4;       // 0 or 4
    // B-tile load mapping (8x128 floats, one float4/thread)
    const int bRow = tid >> 5;            // 0..7
    const int bCol = (tid & 31) * 4;      // 0..124

    const int ty = tid >> 4;              // 0..15
    const int tx = tid & 15;              // 0..15

    float acc[TM][TN] = {};
    float regM[TM], regN[TN];

    for (int k0 = 0; k0 < N_; k0 += BK) {
        const float4 a4 = *reinterpret_cast<const float4*>(Aptr + (size_t)aRow * N_ + k0 + aCol);
        As[aCol + 0][aRow] = a4.x;
        As[aCol + 1][aRow] = a4.y;
        As[aCol + 2][aRow] = a4.z;
        As[aCol + 3][aRow] = a4.w;
        const float4 b4 = *reinterpret_cast<const float4*>(Bptr + (size_t)(k0 + bRow) * NCOL + bCol);
        *reinterpret_cast<float4*>(&Bs[bRow][bCol]) = b4;
        __syncthreads();

        #pragma unroll
        for (int k = 0; k < BK; k++) {
            #pragma unroll
            for (int i = 0; i < TM; i++) regM[i] = As[k][ty * TM + i];
            #pragma unroll
            for (int j = 0; j < TN; j++) regN[j] = Bs[k][tx * TN + j];
            #pragma unroll
            for (int i = 0; i < TM; i++)
                #pragma unroll
                for (int j = 0; j < TN; j++)
                    acc[i][j] += regM[i] * regN[j];
        }
        __syncthreads();
    }

    // Scatter to out[b, n, e]; each 4-wide group stays within one b (8-aligned)
    #pragma unroll
    for (int i = 0; i < TM; i++) {
        const int n = blockRow * BM + ty * TM + i;
        #pragma unroll
        for (int jv = 0; jv < TN; jv += 4) {
            const int col = blockCol * BN + tx * TN + jv;
            const int b = col >> 6;
            const int e = col & 63;
            const float4 v = make_float4(acc[i][jv], acc[i][jv + 1],
                                         acc[i][jv + 2], acc[i][jv + 3]);
            *reinterpret_cast<float4*>(out + ((size_t)b * N_ + n) * D_ + e) = v;
        }
    }
}

// ---------------------------------------------------------------------------
extern "C" void kernel_launch(void* const* d_in, const int* in_sizes, int n_in,
                              void* d_out, int out_size) {
    const float* Z = (const float*)d_in[0];   // [16, 4096, 64]
    const float* A = (const float*)d_in[1];   // [4096, 4096]
    const float* W = (const float*)d_in[2];   // [64, 64]
    float* out = (float*)d_out;               // [16, 4096, 64]

    // Stage 1: X = fold(Z @ W)   (65536 rows / 16 per block)
    zw_kernel<<<(B_ * N_) / 16, 256>>>(Z, W);

    // Stage 2: out = scatter(A @ X)
    dim3 grid(NCOL / BN, N_ / BM);   // (8, 32)
    gemm_ax_kernel<<<grid, 256>>>(A, out);
}

// round 5
// speedup vs baseline: 3.2775x; 3.2775x over previous
#include <cuda_runtime.h>
#include <cstdint>

#define B_    16
#define N_    4096
#define D_    64
#define NCOL  1024

// ---- stage-2 GEMM tiling ----
#define MT      128          // CTA M tile
#define NTI     128          // CTA N tile
#define KT      32           // K chunk
#define STAGES  3
#define NCHUNK  (N_ / KT)    // 128

#define ROWPAD  36           // floats per smem row (32 + 4 pad): conflict-free frags
#define TILEF   (128 * ROWPAD)          // floats per tile (A or B)
#define SSTRF   (2 * TILEF)             // floats per stage
#define SMEM_BYTES (STAGES * SSTRF * 4) // 110592

// scratch (device globals; no allocation allowed)
__device__ float g_Ar[(size_t)N_ * N_];     // rna(A), 64 MB
__device__ float g_Xt[(size_t)NCOL * N_];   // rna((Z@W)^T), 16 MB

// ---------------------------------------------------------------------------
__device__ __forceinline__ uint32_t cvt_tf32(float x) {
    uint32_t r;
    asm("cvt.rna.tf32.f32 %0, %1;" : "=r"(r) : "f"(x));
    return r;
}

__device__ __forceinline__ void cp_async16(void* smem_dst, const void* gmem_src) {
    uint32_t a;
    asm("{ .reg .u64 t; cvta.to.shared.u64 t, %1; cvt.u32.u64 %0, t; }"
        : "=r"(a) : "l"(smem_dst));
    asm volatile("cp.async.cg.shared.global [%0], [%1], 16;"
                 :: "r"(a), "l"(gmem_src) : "memory");
}

#define CP_COMMIT() asm volatile("cp.async.commit_group;" ::: "memory")
#define CP_WAIT1()  asm volatile("cp.async.wait_group 1;" ::: "memory")

__device__ __forceinline__ void mma_tf32(float c[4], const uint32_t a[4],
                                         const uint32_t b[2]) {
    asm volatile(
        "mma.sync.aligned.m16n8k8.row.col.f32.tf32.tf32.f32 "
        "{%0,%1,%2,%3}, {%4,%5,%6,%7}, {%8,%9}, {%0,%1,%2,%3};"
        : "+f"(c[0]), "+f"(c[1]), "+f"(c[2]), "+f"(c[3])
        : "r"(a[0]), "r"(a[1]), "r"(a[2]), "r"(a[3]), "r"(b[0]), "r"(b[1]));
}

// ---------------------------------------------------------------------------
// Stage 0: g_Ar = rna_tf32(A)
// ---------------------------------------------------------------------------
__global__ __launch_bounds__(256) void around_kernel(const float* __restrict__ A) {
    const size_t i = (size_t)blockIdx.x * 256 + threadIdx.x;
    const float4 v = reinterpret_cast<const float4*>(A)[i];
    uint4 t;
    t.x = cvt_tf32(v.x); t.y = cvt_tf32(v.y);
    t.z = cvt_tf32(v.z); t.w = cvt_tf32(v.w);
    reinterpret_cast<uint4*>(g_Ar)[i] = t;
}

// ---------------------------------------------------------------------------
// Stage 1: g_Xt[b*64+e][m] = rna_tf32( sum_d Z[b,m,d] * W[d,e] )  (exact fp32 math)
// ---------------------------------------------------------------------------
__global__ __launch_bounds__(256) void zw_t_kernel(const float* __restrict__ Z,
                                                   const float* __restrict__ W) {
    __shared__ float sW[D_ * D_];
    __shared__ float sZ[64][65];
    const int tid = threadIdx.x;
    const int b = blockIdx.y;
    const int m0 = blockIdx.x * 64;

    for (int i = tid; i < D_ * D_; i += 256) sW[i] = W[i];
    const float4* Zp = reinterpret_cast<const float4*>(Z + ((size_t)b * N_ + m0) * D_);
    for (int f = tid; f < 1024; f += 256) {
        float4 v = Zp[f];
        int r = f >> 4, c = (f & 15) * 4;
        sZ[r][c] = v.x; sZ[r][c + 1] = v.y; sZ[r][c + 2] = v.z; sZ[r][c + 3] = v.w;
    }
    __syncthreads();

    const int tx = tid & 15, ty = tid >> 4;
    float acc[4][4] = {};
    #pragma unroll
    for (int d = 0; d < D_; d++) {
        const float4 w = *reinterpret_cast<const float4*>(&sW[d * D_ + tx * 4]);
        #pragma unroll
        for (int i = 0; i < 4; i++) {
            const float z = sZ[ty * 4 + i][d];
            acc[i][0] += z * w.x; acc[i][1] += z * w.y;
            acc[i][2] += z * w.z; acc[i][3] += z * w.w;
        }
    }
    #pragma unroll
    for (int j = 0; j < 4; j++) {
        const int col = b * D_ + tx * 4 + j;
        uint4 t;
        t.x = cvt_tf32(acc[0][j]); t.y = cvt_tf32(acc[1][j]);
        t.z = cvt_tf32(acc[2][j]); t.w = cvt_tf32(acc[3][j]);
        *reinterpret_cast<uint4*>(g_Xt + (size_t)col * N_ + m0 + ty * 4) = t;
    }
}

// ---------------------------------------------------------------------------
// Stage 2: Y = A @ X via mma.sync tf32.
// CTA 128x128, 8 warps (2x4), warp tile 64x32, 3-stage cp.async pipeline.
// ---------------------------------------------------------------------------
__global__ __launch_bounds__(256, 2)
void gemm_mma_kernel(float* __restrict__ out) {
    extern __shared__ float smem[];
    const int tid = threadIdx.x;
    const int ntile = blockIdx.x;   // 0..7   (128 cols each)
    const int mtile = blockIdx.y;   // 0..31  (128 rows each)

    const float* Abase = g_Ar + (size_t)mtile * MT * N_;
    const float* Bbase = g_Xt + (size_t)ntile * NTI * N_;

    // cp.async mapping: tile = 1024 16B-chunks; thread t does chunks t+256*j.
    // chunk c -> row = c>>3, kc = c&7.
    auto load_stage = [&](int s, int i) {
        const int k0 = i * KT;
        float* As = smem + s * SSTRF;
        float* Bs = As + TILEF;
        #pragma unroll
        for (int j = 0; j < 4; j++) {
            const int c = tid + j * 256;
            const int row = c >> 3, kc = c & 7;
            cp_async16(As + row * ROWPAD + kc * 4,
                       Abase + (size_t)row * N_ + k0 + kc * 4);
        }
        #pragma unroll
        for (int j = 0; j < 4; j++) {
            const int c = tid + j * 256;
            const int row = c >> 3, kc = c & 7;
            cp_async16(Bs + row * ROWPAD + kc * 4,
                       Bbase + (size_t)row * N_ + k0 + kc * 4);
        }
    };

    // Warp layout: 2 (m) x 4 (n); warp tile 64x32.
    const int wid = tid >> 5;
    const int lane = tid & 31;
    const int g = lane >> 2;        // group row
    const int tg = lane & 3;        // thread-in-group
    const int wm0 = (wid >> 2) * 64;
    const int wn0 = (wid & 3) * 32;

    float C[4][4][4] = {};          // [mt][nt][reg]

    // prologue
    load_stage(0, 0); CP_COMMIT();
    load_stage(1, 1); CP_COMMIT();

    for (int i = 0; i < NCHUNK; i++) {
        CP_WAIT1();
        __syncthreads();

        if (i + 2 < NCHUNK) load_stage((i + 2) % STAGES, i + 2);
        CP_COMMIT();   // empty group when no loads issued — keeps counts uniform

        const int s = i % STAGES;
        const float* As = smem + s * SSTRF;
        const float* Bs = As + TILEF;

        #pragma unroll
        for (int kk = 0; kk < 4; kk++) {
            const int kb = kk * 8;
            uint32_t a[4][4];
            #pragma unroll
            for (int mt = 0; mt < 4; mt++) {
                const float* r0 = As + (wm0 + mt * 16 + g) * ROWPAD + kb;
                const float* r1 = r0 + 8 * ROWPAD;
                a[mt][0] = __float_as_uint(r0[tg]);
                a[mt][1] = __float_as_uint(r1[tg]);
                a[mt][2] = __float_as_uint(r0[tg + 4]);
                a[mt][3] = __float_as_uint(r1[tg + 4]);
            }
            uint32_t b[4][2];
            #pragma unroll
            for (int nt = 0; nt < 4; nt++) {
                const float* br = Bs + (wn0 + nt * 8 + g) * ROWPAD + kb;
                b[nt][0] = __float_as_uint(br[tg]);
                b[nt][1] = __float_as_uint(br[tg + 4]);
            }
            #pragma unroll
            for (int mt = 0; mt < 4; mt++)
                #pragma unroll
                for (int nt = 0; nt < 4; nt++)
                    mma_tf32(C[mt][nt], a[mt], b[nt]);
        }
        __syncthreads();
    }

    // ---- epilogue: scatter C to out[b][n][e] ----
    // C frag: rows g,(g+8); cols tg*2, tg*2+1 per (mt,nt) tile.
    #pragma unroll
    for (int mt = 0; mt < 4; mt++) {
        const int row0 = mtile * MT + wm0 + mt * 16 + g;
        #pragma unroll
        for (int nt = 0; nt < 4; nt++) {
            const int col = ntile * NTI + wn0 + nt * 8 + tg * 2;  // even
            const int bb = col >> 6;
            const int e = col & 63;
            float* p = out + ((size_t)bb * N_ + row0) * D_ + e;
            *reinterpret_cast<float2*>(p) = make_float2(C[mt][nt][0], C[mt][nt][1]);
            *reinterpret_cast<float2*>(p + 8 * D_) = make_float2(C[mt][nt][2], C[mt][nt][3]);
        }
    }
}

// ---------------------------------------------------------------------------
extern "C" void kernel_launch(void* const* d_in, const int* in_sizes, int n_in,
                              void* d_out, int out_size) {
    const float* Z = (const float*)d_in[0];   // [16, 4096, 64]
    const float* A = (const float*)d_in[1];   // [4096, 4096]
    const float* W = (const float*)d_in[2];   // [64, 64]
    float* out = (float*)d_out;               // [16, 4096, 64]

    around_kernel<<<(N_ * (size_t)N_) / (4 * 256), 256>>>(A);
    zw_t_kernel<<<dim3(N_ / 64, B_), 256>>>(Z, W);

    cudaFuncSetAttribute(gemm_mma_kernel,
                         cudaFuncAttributeMaxDynamicSharedMemorySize, SMEM_BYTES);
    gemm_mma_kernel<<<dim3(NCOL / NTI, N_ / MT), 256, SMEM_BYTES>>>(out);
}

// round 7
// speedup vs baseline: 3.9207x; 1.1962x over previous
#include <cuda_runtime.h>
#include <cstdint>

#define B_    16
#define N_    4096
#define D_    64
#define NCOL  1024

// ---- stage-2 GEMM tiling ----
#define MT      128          // CTA M tile
#define NTI     128          // CTA N tile
#define KT      32           // K chunk
#define STAGES  3
#define NCHUNK  (N_ / KT)    // 128

#define TILEF   4096                    // floats per tile per stage (16 KB)
#define SSTRF   (2 * TILEF)             // floats per stage (A + B)
#define SMEM_BYTES (STAGES * SSTRF * 4) // 98304

// scratch (device globals; no allocation allowed)
// g_Ar: rna(A) permuted to fragment order:
//   [mtile 32][kc 128][mb 8][k8 4][lane 32][4 floats]
//   lane quad = (A[r0][c0], A[r0+8][c0], A[r0][c0+4], A[r0+8][c0+4]),
//   r0 = mtile*128+mb*16+(lane>>2), c0 = kc*32+k8*8+(lane&3)
__device__ float g_Ar[(size_t)N_ * N_];     // 64 MB
// g_X: plain row-major X[m][n] = rna((Z@W) folded), n = b*64+e
__device__ float g_X[(size_t)N_ * NCOL];    // 16 MB
// g_Xt: X permuted to B-fragment order:
//   [ntile 8][kc 128][nb 16][k8 4][lane 32][2 floats]
//   lane pair = (X[m][n], X[m+4][n]), n = ntile*128+nb*8+(lane>>2),
//   m = kc*32+k8*8+(lane&3)
__device__ float g_Xt[(size_t)NCOL * N_];   // 16 MB

// ---------------------------------------------------------------------------
__device__ __forceinline__ uint32_t cvt_tf32(float x) {
    uint32_t r;
    asm("cvt.rna.tf32.f32 %0, %1;" : "=r"(r) : "f"(x));
    return r;
}

__device__ __forceinline__ void cp_async16(void* smem_dst, const void* gmem_src) {
    uint32_t a;
    asm("{ .reg .u64 t; cvta.to.shared.u64 t, %1; cvt.u32.u64 %0, t; }"
        : "=r"(a) : "l"(smem_dst));
    asm volatile("cp.async.cg.shared.global [%0], [%1], 16;"
                 :: "r"(a), "l"(gmem_src) : "memory");
}

#define CP_COMMIT() asm volatile("cp.async.commit_group;" ::: "memory")
#define CP_WAIT1()  asm volatile("cp.async.wait_group 1;" ::: "memory")

__device__ __forceinline__ void mma_tf32(float c[4], const uint32_t a[4],
                                         const uint32_t b[2]) {
    asm volatile(
        "mma.sync.aligned.m16n8k8.row.col.f32.tf32.tf32.f32 "
        "{%0,%1,%2,%3}, {%4,%5,%6,%7}, {%8,%9}, {%0,%1,%2,%3};"
        : "+f"(c[0]), "+f"(c[1]), "+f"(c[2]), "+f"(c[3])
        : "r"(a[0]), "r"(a[1]), "r"(a[2]), "r"(a[3]), "r"(b[0]), "r"(b[1]));
}

// ---------------------------------------------------------------------------
// Prep A: g_Ar = fragment-permuted rna(A). One float4 group per thread.
// ---------------------------------------------------------------------------
__global__ __launch_bounds__(256) void around_kernel(const float* __restrict__ A) {
    const uint32_t idx = blockIdx.x * 256 + threadIdx.x;   // 0 .. 4194303
    const int lane  = idx & 31;
    const int k8    = (idx >> 5) & 3;
    const int mb    = (idx >> 7) & 7;
    const int kc    = (idx >> 10) & 127;
    const int mtile = idx >> 17;
    const int g = lane >> 2, tg = lane & 3;

    const int r0 = mtile * 128 + mb * 16 + g;
    const int c0 = kc * 32 + k8 * 8 + tg;
    const float* p = A + (size_t)r0 * N_ + c0;
    uint4 t;
    t.x = cvt_tf32(p[0]);
    t.y = cvt_tf32(p[8 * N_]);
    t.z = cvt_tf32(p[4]);
    t.w = cvt_tf32(p[8 * N_ + 4]);
    reinterpret_cast<uint4*>(g_Ar)[idx] = t;
}

// ---------------------------------------------------------------------------
// Stage 1: g_X[m][n] = rna_tf32( sum_d Z[b,m,d] * W[d,e] ), n = b*64+e.
// ---------------------------------------------------------------------------
__global__ __launch_bounds__(256) void zw_kernel(const float* __restrict__ Z,
                                                 const float* __restrict__ W) {
    __shared__ float sW[D_ * D_];
    __shared__ float sZ[64][65];
    const int tid = threadIdx.x;
    const int b = blockIdx.y;
    const int m0 = blockIdx.x * 64;

    for (int i = tid; i < D_ * D_; i += 256) sW[i] = W[i];
    const float4* Zp = reinterpret_cast<const float4*>(Z + ((size_t)b * N_ + m0) * D_);
    for (int f = tid; f < 1024; f += 256) {
        float4 v = Zp[f];
        int r = f >> 4, c = (f & 15) * 4;
        sZ[r][c] = v.x; sZ[r][c + 1] = v.y; sZ[r][c + 2] = v.z; sZ[r][c + 3] = v.w;
    }
    __syncthreads();

    const int tx = tid & 15, ty = tid >> 4;
    float acc[4][4] = {};
    #pragma unroll
    for (int d = 0; d < D_; d++) {
        const float4 w = *reinterpret_cast<const float4*>(&sW[d * D_ + tx * 4]);
        #pragma unroll
        for (int i = 0; i < 4; i++) {
            const float z = sZ[ty * 4 + i][d];
            acc[i][0] += z * w.x; acc[i][1] += z * w.y;
            acc[i][2] += z * w.z; acc[i][3] += z * w.w;
        }
    }
    #pragma unroll
    for (int i = 0; i < 4; i++) {
        const int m = m0 + ty * 4 + i;
        uint4 t;
        t.x = cvt_tf32(acc[i][0]); t.y = cvt_tf32(acc[i][1]);
        t.z = cvt_tf32(acc[i][2]); t.w = cvt_tf32(acc[i][3]);
        *reinterpret_cast<uint4*>(g_X + (size_t)m * NCOL + b * D_ + tx * 4) = t;
    }
}

// ---------------------------------------------------------------------------
// Prep B: g_Xt = fragment-permuted g_X. One float2 per thread.
// ---------------------------------------------------------------------------
__global__ __launch_bounds__(256) void permb_kernel() {
    const uint32_t idx = blockIdx.x * 256 + threadIdx.x;   // 0 .. 2097151
    const int lane  = idx & 31;
    const int k8    = (idx >> 5) & 3;
    const int nb    = (idx >> 7) & 15;
    const int kc    = (idx >> 11) & 127;
    const int ntile = idx >> 18;
    const int g = lane >> 2, tg = lane & 3;

    const int n = ntile * 128 + nb * 8 + g;
    const int m = kc * 32 + k8 * 8 + tg;
    float2 v;
    v.x = g_X[(size_t)m * NCOL + n];
    v.y = g_X[(size_t)(m + 4) * NCOL + n];
    reinterpret_cast<float2*>(g_Xt)[idx] = v;
}

// ---------------------------------------------------------------------------
// Stage 2: Y = A @ X via mma.sync tf32. CTA 128x128, 8 warps (2x4),
// warp tile 64x32, 3-stage cp.async pipeline, fragment-native smem.
// ---------------------------------------------------------------------------
__global__ __launch_bounds__(256, 2)
void gemm_mma_kernel(float* __restrict__ out) {
    extern __shared__ __align__(16) float smem[];
    const int tid = threadIdx.x;
    const int ntile = blockIdx.x;   // 0..7
    const int mtile = blockIdx.y;   // 0..31

    const float4* Abase = reinterpret_cast<const float4*>(g_Ar)
                        + (size_t)mtile * 128 * 1024;        // [kc][1024 f4]
    const float4* Bbase = reinterpret_cast<const float4*>(g_Xt)
                        + (size_t)ntile * 128 * 1024;        // [kc][1024 f4]

    auto load_stage = [&](int s, int i) {
        float4* As4 = reinterpret_cast<float4*>(smem + s * SSTRF);
        float4* Bs4 = As4 + 1024;
        const float4* Ag = Abase + (size_t)i * 1024;
        const float4* Bg = Bbase + (size_t)i * 1024;
        #pragma unroll
        for (int j = 0; j < 4; j++) {
            const int c = tid + j * 256;
            cp_async16(As4 + c, Ag + c);
        }
        #pragma unroll
        for (int j = 0; j < 4; j++) {
            const int c = tid + j * 256;
            cp_async16(Bs4 + c, Bg + c);
        }
    };

    // Warp layout: 2 (m) x 4 (n); warp tile 64x32.
    const int wid = tid >> 5;
    const int lane = tid & 31;
    const int g = lane >> 2;
    const int tg = lane & 3;
    const int mbw = (wid >> 2) * 4;      // first mb block (of 16 rows) for warp
    const int nbw = (wid & 3) * 4;       // first nb block (of 8 cols) for warp

    float C[4][4][4] = {};               // [mt][nt][reg]

    load_stage(0, 0); CP_COMMIT();
    load_stage(1, 1); CP_COMMIT();

    for (int i = 0; i < NCHUNK; i++) {
        CP_WAIT1();
        __syncthreads();

        if (i + 2 < NCHUNK) load_stage((i + 2) % STAGES, i + 2);
        CP_COMMIT();

        const int s = i % STAGES;
        const float* As = smem + s * SSTRF;
        const float* Bs = As + TILEF;

        #pragma unroll
        for (int kk = 0; kk < 4; kk++) {
            uint32_t a[4][4];
            #pragma unroll
            for (int mt = 0; mt < 4; mt++) {
                const float4 av = *reinterpret_cast<const float4*>(
                    As + (mbw + mt) * 512 + kk * 128 + lane * 4);
                a[mt][0] = __float_as_uint(av.x);
                a[mt][1] = __float_as_uint(av.y);
                a[mt][2] = __float_as_uint(av.z);
                a[mt][3] = __float_as_uint(av.w);
            }
            uint32_t b[4][2];
            #pragma unroll
            for (int nt = 0; nt < 4; nt++) {
                const float2 bv = *reinterpret_cast<const float2*>(
                    Bs + (nbw + nt) * 256 + kk * 64 + lane * 2);
                b[nt][0] = __float_as_uint(bv.x);
                b[nt][1] = __float_as_uint(bv.y);
            }
            #pragma unroll
            for (int mt = 0; mt < 4; mt++)
                #pragma unroll
                for (int nt = 0; nt < 4; nt++)
                    mma_tf32(C[mt][nt], a[mt], b[nt]);
        }
        // NOTE: no end-of-loop barrier needed — the next iteration's
        // post-WAIT barrier orders compute(i) before load(i+3).
    }

    // ---- epilogue: scatter C to out[b][n][e] ----
    #pragma unroll
    for (int mt = 0; mt < 4; mt++) {
        const int row0 = mtile * MT + (mbw + mt) * 16 + g;
        #pragma unroll
        for (int nt = 0; nt < 4; nt++) {
            const int col = ntile * NTI + (nbw + nt) * 8 + tg * 2;  // even
            const int bb = col >> 6;
            const int e = col & 63;
            float* p = out + ((size_t)bb * N_ + row0) * D_ + e;
            *reinterpret_cast<float2*>(p) = make_float2(C[mt][nt][0], C[mt][nt][1]);
            *reinterpret_cast<float2*>(p + 8 * D_) = make_float2(C[mt][nt][2], C[mt][nt][3]);
        }
    }
}

// ---------------------------------------------------------------------------
extern "C" void kernel_launch(void* const* d_in, const int* in_sizes, int n_in,
                              void* d_out, int out_size) {
    const float* Z = (const float*)d_in[0];   // [16, 4096, 64]
    const float* A = (const float*)d_in[1];   // [4096, 4096]
    const float* W = (const float*)d_in[2];   // [64, 64]
    float* out = (float*)d_out;               // [16, 4096, 64]

    around_kernel<<<(N_ * (size_t)N_) / (4 * 256), 256>>>(A);
    zw_kernel<<<dim3(N_ / 64, B_), 256>>>(Z, W);
    permb_kernel<<<((size_t)NCOL * N_) / (2 * 256), 256>>>();

    cudaFuncSetAttribute(gemm_mma_kernel,
                         cudaFuncAttributeMaxDynamicSharedMemorySize, SMEM_BYTES);
    gemm_mma_kernel<<<dim3(NCOL / NTI, N_ / MT), 256, SMEM_BYTES>>>(out);
}

// round 8
// speedup vs baseline: 6.5227x; 1.6637x over previous
#include <cuda_runtime.h>
#include <cuda_fp16.h>
#include <cstdint>

#define B_    16
#define N_    4096
#define D_    64
#define NCOL  1024

// ---- stage-2 GEMM tiling (fp16 operands, fp32 accum) ----
#define MT      128          // CTA M tile
#define NTI     128          // CTA N tile
#define KT      64           // K chunk (4 x k16 steps)
#define STAGES  3
#define NCHUNK  (N_ / KT)    // 64

#define STAGE_U4  2048                   // uint4 per stage (A 1024 + B 1024) = 32 KB
#define SMEM_BYTES (STAGES * STAGE_U4 * 16)  // 98304

// ---- scratch (device globals) ----
// g_Ah: A in fp16, fragment order for mma.m16n8k16:
//   [mtile 32][kc 64][mb 8][k16 4][lane 32] x uint4 (4 half2 regs a0..a3)
//   a0=(r0,c0:c0+1) a1=(r0+8,c0:c0+1) a2=(r0,c0+8:c0+9) a3=(r0+8,c0+8:c0+9)
//   r0 = mtile*128+mb*16+(lane>>2), c0 = kc*64+k16*16+(lane&3)*2
__device__ uint4 g_Ah[(size_t)32 * 64 * 8 * 4 * 32];          // 32 MB
// g_Xth[n][m] = fp16 of rna-free rn( (Z@W) folded ), transposed row-major
__device__ __half g_Xth[(size_t)NCOL * N_];                   // 8 MB
// g_Xb: X in B-fragment order:
//   [ntile 8][kc 64][nb 16][k16 4][lane 32] x uint2 (2 half2 regs b0,b1)
//   b0=(k0+2tg:k0+2tg+1, n) b1=(k0+2tg+8:+9, n); n = ntile*128+nb*8+(lane>>2)
__device__ uint2 g_Xb[(size_t)8 * 64 * 16 * 4 * 32];          // 8 MB

// ---------------------------------------------------------------------------
__device__ __forceinline__ void cp_async16(void* smem_dst, const void* gmem_src) {
    uint32_t a;
    asm("{ .reg .u64 t; cvta.to.shared.u64 t, %1; cvt.u32.u64 %0, t; }"
        : "=r"(a) : "l"(smem_dst));
    asm volatile("cp.async.cg.shared.global [%0], [%1], 16;"
                 :: "r"(a), "l"(gmem_src) : "memory");
}
#define CP_COMMIT() asm volatile("cp.async.commit_group;" ::: "memory")
#define CP_WAIT1()  asm volatile("cp.async.wait_group 1;" ::: "memory")

__device__ __forceinline__ void mma_f16(float c[4], const uint32_t a[4],
                                        const uint32_t b[2]) {
    asm volatile(
        "mma.sync.aligned.m16n8k16.row.col.f32.f16.f16.f32 "
        "{%0,%1,%2,%3}, {%4,%5,%6,%7}, {%8,%9}, {%0,%1,%2,%3};"
        : "+f"(c[0]), "+f"(c[1]), "+f"(c[2]), "+f"(c[3])
        : "r"(a[0]), "r"(a[1]), "r"(a[2]), "r"(a[3]), "r"(b[0]), "r"(b[1]));
}

__device__ __forceinline__ uint32_t pack_h2(float lo, float hi) {
    const __half2 h = __floats2half2_rn(lo, hi);   // lo -> low 16 bits
    return *reinterpret_cast<const uint32_t*>(&h);
}

// ---------------------------------------------------------------------------
// Prep A: g_Ah = fragment-ordered fp16(A). One uint4 per thread.
// ---------------------------------------------------------------------------
__global__ __launch_bounds__(256) void aprep_kernel(const float* __restrict__ A) {
    const uint32_t idx = blockIdx.x * 256 + threadIdx.x;   // 0 .. 2097151
    const int lane  = idx & 31;
    const int k16   = (idx >> 5) & 3;
    const int mb    = (idx >> 7) & 7;
    const int kc    = (idx >> 10) & 63;
    const int mtile = idx >> 16;
    const int g = lane >> 2, tg = lane & 3;

    const int r0 = mtile * 128 + mb * 16 + g;
    const int c0 = kc * 64 + k16 * 16 + tg * 2;
    const float* p = A + (size_t)r0 * N_ + c0;

    const float2 v0 = *reinterpret_cast<const float2*>(p);              // (r0,   c0)
    const float2 v1 = *reinterpret_cast<const float2*>(p + 8 * N_);     // (r0+8, c0)
    const float2 v2 = *reinterpret_cast<const float2*>(p + 8);          // (r0,   c0+8)
    const float2 v3 = *reinterpret_cast<const float2*>(p + 8 * N_ + 8); // (r0+8, c0+8)

    uint4 t;
    t.x = pack_h2(v0.x, v0.y);
    t.y = pack_h2(v1.x, v1.y);
    t.z = pack_h2(v2.x, v2.y);
    t.w = pack_h2(v3.x, v3.y);
    g_Ah[idx] = t;
}

// ---------------------------------------------------------------------------
// Stage 1: g_Xth[n][m] = fp16( sum_d Z[b,m,d] * W[d,e] ), n = b*64+e (exact fp32 math)
// ---------------------------------------------------------------------------
__global__ __launch_bounds__(256) void zw_kernel(const float* __restrict__ Z,
                                                 const float* __restrict__ W) {
    __shared__ float sW[D_ * D_];
    __shared__ float sZ[64][65];
    const int tid = threadIdx.x;
    const int b = blockIdx.y;
    const int m0 = blockIdx.x * 64;

    for (int i = tid; i < D_ * D_; i += 256) sW[i] = W[i];
    const float4* Zp = reinterpret_cast<const float4*>(Z + ((size_t)b * N_ + m0) * D_);
    for (int f = tid; f < 1024; f += 256) {
        float4 v = Zp[f];
        int r = f >> 4, c = (f & 15) * 4;
        sZ[r][c] = v.x; sZ[r][c + 1] = v.y; sZ[r][c + 2] = v.z; sZ[r][c + 3] = v.w;
    }
    __syncthreads();

    const int tx = tid & 15, ty = tid >> 4;
    float acc[4][4] = {};
    #pragma unroll
    for (int d = 0; d < D_; d++) {
        const float4 w = *reinterpret_cast<const float4*>(&sW[d * D_ + tx * 4]);
        #pragma unroll
        for (int i = 0; i < 4; i++) {
            const float z = sZ[ty * 4 + i][d];
            acc[i][0] += z * w.x; acc[i][1] += z * w.y;
            acc[i][2] += z * w.z; acc[i][3] += z * w.w;
        }
    }
    // transposed fp16 write: 4 consecutive m per (n) as uint2
    #pragma unroll
    for (int j = 0; j < 4; j++) {
        const int n = b * D_ + tx * 4 + j;
        uint2 t;
        t.x = pack_h2(acc[0][j], acc[1][j]);
        t.y = pack_h2(acc[2][j], acc[3][j]);
        *reinterpret_cast<uint2*>(g_Xth + (size_t)n * N_ + m0 + ty * 4) = t;
    }
}

// ---------------------------------------------------------------------------
// Prep B: g_Xb = B-fragment-ordered g_Xth. One uint2 per thread.
// ---------------------------------------------------------------------------
__global__ __launch_bounds__(256) void permb_kernel() {
    const uint32_t idx = blockIdx.x * 256 + threadIdx.x;   // 0 .. 1048575
    const int lane  = idx & 31;
    const int k16   = (idx >> 5) & 3;
    const int nb    = (idx >> 7) & 15;
    const int kc    = (idx >> 11) & 63;
    const int ntile = idx >> 17;
    const int g = lane >> 2, tg = lane & 3;

    const int n = ntile * 128 + nb * 8 + g;
    const int k0 = kc * 64 + k16 * 16 + tg * 2;
    const __half* p = g_Xth + (size_t)n * N_ + k0;
    uint2 t;
    t.x = *reinterpret_cast<const uint32_t*>(p);       // (k0, k0+1)
    t.y = *reinterpret_cast<const uint32_t*>(p + 8);   // (k0+8, k0+9)
    g_Xb[idx] = t;
}

// ---------------------------------------------------------------------------
// Stage 2: Y = A @ X via mma.sync fp16/f32. CTA 128x128, 8 warps (2x4),
// warp tile 64x32, K-chunk 64, 3-stage cp.async pipeline, fragment smem.
// ---------------------------------------------------------------------------
__global__ __launch_bounds__(256, 2)
void gemm_mma_kernel(float* __restrict__ out) {
    extern __shared__ __align__(16) uint4 smem[];
    const int tid = threadIdx.x;
    const int ntile = blockIdx.x;   // 0..7
    const int mtile = blockIdx.y;   // 0..31

    const uint4* Abase = g_Ah + (size_t)mtile * 64 * 1024;              // [kc][1024 u4]
    const uint4* Bbase = reinterpret_cast<const uint4*>(g_Xb)
                       + (size_t)ntile * 64 * 1024;                     // [kc][1024 u4]

    auto load_stage = [&](int s, int i) {
        uint4* As4 = smem + s * STAGE_U4;
        uint4* Bs4 = As4 + 1024;
        const uint4* Ag = Abase + (size_t)i * 1024;
        const uint4* Bg = Bbase + (size_t)i * 1024;
        #pragma unroll
        for (int j = 0; j < 4; j++) cp_async16(As4 + tid + j * 256, Ag + tid + j * 256);
        #pragma unroll
        for (int j = 0; j < 4; j++) cp_async16(Bs4 + tid + j * 256, Bg + tid + j * 256);
    };

    const int wid = tid >> 5;
    const int lane = tid & 31;
    const int g = lane >> 2;
    const int tg = lane & 3;
    const int mbw = (wid >> 2) * 4;      // first 16-row block for warp (0 or 4)
    const int nbw = (wid & 3) * 4;       // first 8-col block for warp (0,4,8,12)

    float C[4][4][4] = {};               // [mt][nt][reg]

    load_stage(0, 0); CP_COMMIT();
    load_stage(1, 1); CP_COMMIT();

    for (int i = 0; i < NCHUNK; i++) {
        CP_WAIT1();
        __syncthreads();

        if (i + 2 < NCHUNK) load_stage((i + 2) % STAGES, i + 2);
        CP_COMMIT();

        const int s = i % STAGES;
        const uint4* As4 = smem + s * STAGE_U4;
        const uint2* Bs2 = reinterpret_cast<const uint2*>(As4 + 1024);

        #pragma unroll
        for (int kk = 0; kk < 4; kk++) {
            uint32_t a[4][4];
            #pragma unroll
            for (int mt = 0; mt < 4; mt++) {
                const uint4 av = As4[((mbw + mt) * 4 + kk) * 32 + lane];
                a[mt][0] = av.x; a[mt][1] = av.y; a[mt][2] = av.z; a[mt][3] = av.w;
            }
            uint32_t b[4][2];
            #pragma unroll
            for (int nt = 0; nt < 4; nt++) {
                const uint2 bv = Bs2[((nbw + nt) * 4 + kk) * 32 + lane];
                b[nt][0] = bv.x; b[nt][1] = bv.y;
            }
            #pragma unroll
            for (int mt = 0; mt < 4; mt++)
                #pragma unroll
                for (int nt = 0; nt < 4; nt++)
                    mma_f16(C[mt][nt], a[mt], b[nt]);
        }
        // next iteration's post-WAIT barrier orders compute(i) before load(i+3)
    }

    // ---- epilogue: scatter C to out[b][n][e] ----
    #pragma unroll
    for (int mt = 0; mt < 4; mt++) {
        const int row0 = mtile * MT + (mbw + mt) * 16 + g;
        #pragma unroll
        for (int nt = 0; nt < 4; nt++) {
            const int col = ntile * NTI + (nbw + nt) * 8 + tg * 2;  // even
            const int bb = col >> 6;
            const int e = col & 63;
            float* p = out + ((size_t)bb * N_ + row0) * D_ + e;
            *reinterpret_cast<float2*>(p) = make_float2(C[mt][nt][0], C[mt][nt][1]);
            *reinterpret_cast<float2*>(p + 8 * D_) = make_float2(C[mt][nt][2], C[mt][nt][3]);
        }
    }
}

// ---------------------------------------------------------------------------
extern "C" void kernel_launch(void* const* d_in, const int* in_sizes, int n_in,
                              void* d_out, int out_size) {
    const float* Z = (const float*)d_in[0];   // [16, 4096, 64]
    const float* A = (const float*)d_in[1];   // [4096, 4096]
    const float* W = (const float*)d_in[2];   // [64, 64]
    float* out = (float*)d_out;               // [16, 4096, 64]

    aprep_kernel<<<2097152 / 256, 256>>>(A);
    zw_kernel<<<dim3(N_ / 64, B_), 256>>>(Z, W);
    permb_kernel<<<1048576 / 256, 256>>>();

    cudaFuncSetAttribute(gemm_mma_kernel,
                         cudaFuncAttributeMaxDynamicSharedMemorySize, SMEM_BYTES);
    gemm_mma_kernel<<<dim3(NCOL / NTI, N_ / MT), 256, SMEM_BYTES>>>(out);
}

// round 11
// speedup vs baseline: 6.8021x; 1.0428x over previous
#include <cuda_runtime.h>
#include <cuda_fp16.h>
#include <cstdint>

#define B_    16
#define N_    4096
#define D_    64
#define NCOL  1024

// ---- stage-2 GEMM tiling (fp16 operands, fp32 accum) ----
#define MT      128          // CTA M tile
#define NTI     256          // CTA N tile
#define KT      64           // K chunk (4 x k16 steps)
#define STAGES  4
#define NCHUNK  (N_ / KT)    // 64

#define A_U4      1024                   // uint4 of A per stage (16 KB)
#define B_U4      2048                   // uint4 of B per stage (32 KB)
#define STAGE_U4  (A_U4 + B_U4)          // 3072 (48 KB)
#define SMEM_BYTES (STAGES * STAGE_U4 * 16)   // 196608

// ---- scratch (device globals) ----
// g_Ah: A in fp16, fragment order for mma.m16n8k16 (MT=128):
//   [mtile 32][kc 64][mb 8][k16 4][lane 32] x uint4 (regs a0..a3)
//   a0=(r0,c0:c0+1) a1=(r0+8,c0:c0+1) a2=(r0,c0+8:+9) a3=(r0+8,c0+8:+9)
//   r0 = mtile*128+mb*16+(lane>>2), c0 = kc*64+k16*16+(lane&3)*2
__device__ uint4 g_Ah[(size_t)32 * 64 * 8 * 4 * 32];          // 32 MB
// g_Xb: X in B-fragment order (NTI=256):
//   [ntile 4][kc 64][nb 32][k16 4][lane 32] x uint2 (regs b0,b1)
//   b0=(k0+2tg, k0+2tg+1 ; n)  b1=(+8,+9 ; n)
//   n = ntile*256+nb*8+(lane>>2), k0 = kc*64+k16*16
__device__ uint2 g_Xb[(size_t)4 * 64 * 32 * 4 * 32];          // 8 MB

// ---------------------------------------------------------------------------
__device__ __forceinline__ void cp_async16(void* smem_dst, const void* gmem_src) {
    uint32_t a;
    asm("{ .reg .u64 t; cvta.to.shared.u64 t, %1; cvt.u32.u64 %0, t; }"
        : "=r"(a) : "l"(smem_dst));
    asm volatile("cp.async.cg.shared.global [%0], [%1], 16;"
                 :: "r"(a), "l"(gmem_src) : "memory");
}
#define CP_COMMIT() asm volatile("cp.async.commit_group;" ::: "memory")
#define CP_WAIT2()  asm volatile("cp.async.wait_group 2;" ::: "memory")

__device__ __forceinline__ void mma_f16(float c[4], const uint32_t a[4],
                                        const uint32_t b[2]) {
    asm volatile(
        "mma.sync.aligned.m16n8k16.row.col.f32.f16.f16.f32 "
        "{%0,%1,%2,%3}, {%4,%5,%6,%7}, {%8,%9}, {%0,%1,%2,%3};"
        : "+f"(c[0]), "+f"(c[1]), "+f"(c[2]), "+f"(c[3])
        : "r"(a[0]), "r"(a[1]), "r"(a[2]), "r"(a[3]), "r"(b[0]), "r"(b[1]));
}

__device__ __forceinline__ uint32_t pack_h2(float lo, float hi) {
    const __half2 h = __floats2half2_rn(lo, hi);   // lo -> low 16 bits
    return *reinterpret_cast<const uint32_t*>(&h);
}

// ---------------------------------------------------------------------------
// Prep A: g_Ah = fragment-ordered fp16(A). One uint4 per thread.
// ---------------------------------------------------------------------------
__global__ __launch_bounds__(256) void aprep_kernel(const float* __restrict__ A) {
    const uint32_t idx = blockIdx.x * 256 + threadIdx.x;   // 0 .. 2097151
    const int lane  = idx & 31;
    const int k16   = (idx >> 5) & 3;
    const int mb    = (idx >> 7) & 7;
    const int kc    = (idx >> 10) & 63;
    const int mtile = idx >> 16;
    const int g = lane >> 2, tg = lane & 3;

    const int r0 = mtile * 128 + mb * 16 + g;
    const int c0 = kc * 64 + k16 * 16 + tg * 2;
    const float* p = A + (size_t)r0 * N_ + c0;

    const float2 v0 = *reinterpret_cast<const float2*>(p);
    const float2 v1 = *reinterpret_cast<const float2*>(p + 8 * N_);
    const float2 v2 = *reinterpret_cast<const float2*>(p + 8);
    const float2 v3 = *reinterpret_cast<const float2*>(p + 8 * N_ + 8);

    uint4 t;
    t.x = pack_h2(v0.x, v0.y);
    t.y = pack_h2(v1.x, v1.y);
    t.z = pack_h2(v2.x, v2.y);
    t.w = pack_h2(v3.x, v3.y);
    g_Ah[idx] = t;
}

// ---------------------------------------------------------------------------
// Stage 1 (fused): X tile = Z@W (exact fp32), then write B-fragments directly.
// Block (blockIdx.x = m-tile of 64 = kc, blockIdx.y = b) covers exactly the
// fragment region (ntile = b>>2, nb base = (b&3)*8, all 4 k16, all lanes).
// ---------------------------------------------------------------------------
__global__ __launch_bounds__(256) void zw_kernel(const float* __restrict__ Z,
                                                 const float* __restrict__ W) {
    __shared__ float sW[D_ * D_];
    __shared__ float sZ[64][65];
    __shared__ __half sXT[64][72];   // [n_local][m_local], pad 72 -> conflict-free
    const int tid = threadIdx.x;
    const int b = blockIdx.y;
    const int kc = blockIdx.x;
    const int m0 = kc * 64;

    for (int i = tid; i < D_ * D_; i += 256) sW[i] = W[i];
    const float4* Zp = reinterpret_cast<const float4*>(Z + ((size_t)b * N_ + m0) * D_);
    for (int f = tid; f < 1024; f += 256) {
        float4 v = Zp[f];
        int r = f >> 4, c = (f & 15) * 4;
        sZ[r][c] = v.x; sZ[r][c + 1] = v.y; sZ[r][c + 2] = v.z; sZ[r][c + 3] = v.w;
    }
    __syncthreads();

    const int tx = tid & 15, ty = tid >> 4;
    float acc[4][4] = {};
    #pragma unroll
    for (int d = 0; d < D_; d++) {
        const float4 w = *reinterpret_cast<const float4*>(&sW[d * D_ + tx * 4]);
        #pragma unroll
        for (int i = 0; i < 4; i++) {
            const float z = sZ[ty * 4 + i][d];
            acc[i][0] += z * w.x; acc[i][1] += z * w.y;
            acc[i][2] += z * w.z; acc[i][3] += z * w.w;
        }
    }
    // sXT[n_local][m_local] = fp16(X[m0+m_local][b*64+n_local])
    #pragma unroll
    for (int j = 0; j < 4; j++) {
        const uint32_t h0 = pack_h2(acc[0][j], acc[1][j]);
        const uint32_t h1 = pack_h2(acc[2][j], acc[3][j]);
        *reinterpret_cast<uint32_t*>(&sXT[tx * 4 + j][ty * 4])     = h0;
        *reinterpret_cast<uint32_t*>(&sXT[tx * 4 + j][ty * 4 + 2]) = h1;
    }
    __syncthreads();

    // fragment write: 1024 uint2 per block, 4 per thread
    const size_t base = (((size_t)(b >> 2) * 64 + kc) * 32 + (b & 3) * 8) * 128;
    #pragma unroll
    for (int it = 0; it < 4; it++) {
        const int f = tid + it * 256;              // nbl*128 + k16*32 + lane
        const int lane = f & 31;
        const int k16 = (f >> 5) & 3;
        const int nbl = f >> 7;
        const int n_local = nbl * 8 + (lane >> 2);
        const int k_local = k16 * 16 + (lane & 3) * 2;
        uint2 t;
        t.x = *reinterpret_cast<const uint32_t*>(&sXT[n_local][k_local]);
        t.y = *reinterpret_cast<const uint32_t*>(&sXT[n_local][k_local + 8]);
        g_Xb[base + f] = t;
    }
}

// ---------------------------------------------------------------------------
// Stage 2: Y = A @ X via mma.sync fp16/f32. CTA 128x256, 8 warps (2x4),
// warp tile 64x64, K-chunk 64, 4-stage cp.async pipeline, fragment smem.
// ---------------------------------------------------------------------------
__global__ __launch_bounds__(256, 1)
void gemm_mma_kernel(float* __restrict__ out) {
    extern __shared__ __align__(16) uint4 smem[];
    const int tid = threadIdx.x;
    const int ntile = blockIdx.x;   // 0..3
    const int mtile = blockIdx.y;   // 0..31

    const uint4* Abase = g_Ah + (size_t)mtile * 64 * A_U4;              // [kc][1024 u4]
    const uint4* Bbase = reinterpret_cast<const uint4*>(g_Xb)
                       + (size_t)ntile * 64 * B_U4;                     // [kc][2048 u4]

    auto load_stage = [&](int s, int i) {
        uint4* As4 = smem + s * STAGE_U4;
        uint4* Bs4 = As4 + A_U4;
        const uint4* Ag = Abase + (size_t)i * A_U4;
        const uint4* Bg = Bbase + (size_t)i * B_U4;
        #pragma unroll
        for (int j = 0; j < 4; j++) cp_async16(As4 + tid + j * 256, Ag + tid + j * 256);
        #pragma unroll
        for (int j = 0; j < 8; j++) cp_async16(Bs4 + tid + j * 256, Bg + tid + j * 256);
    };

    const int wid = tid >> 5;
    const int lane = tid & 31;
    const int g = lane >> 2;
    const int tg = lane & 3;
    const int mbw = (wid >> 2) * 4;      // first 16-row block for warp (0 or 4)
    const int nbw = (wid & 3) * 8;       // first 8-col block for warp (0,8,16,24)

    float C[4][8][4] = {};               // [mt][nt][reg] — 128 regs

    load_stage(0, 0); CP_COMMIT();
    load_stage(1, 1); CP_COMMIT();
    load_stage(2, 2); CP_COMMIT();

    for (int i = 0; i < NCHUNK; i++) {
        CP_WAIT2();
        __syncthreads();

        if (i + 3 < NCHUNK) load_stage((i + 3) % STAGES, i + 3);
        CP_COMMIT();

        const int s = i % STAGES;
        const uint4* As4 = smem + s * STAGE_U4;
        const uint2* Bs2 = reinterpret_cast<const uint2*>(As4 + A_U4);

        #pragma unroll
        for (int kk = 0; kk < 4; kk++) {
            uint32_t a[4][4];
            #pragma unroll
            for (int mt = 0; mt < 4; mt++) {
                const uint4 av = As4[((mbw + mt) * 4 + kk) * 32 + lane];
                a[mt][0] = av.x; a[mt][1] = av.y; a[mt][2] = av.z; a[mt][3] = av.w;
            }
            uint32_t b[8][2];
            #pragma unroll
            for (int nt = 0; nt < 8; nt++) {
                const uint2 bv = Bs2[((nbw + nt) * 4 + kk) * 32 + lane];
                b[nt][0] = bv.x; b[nt][1] = bv.y;
            }
            #pragma unroll
            for (int mt = 0; mt < 4; mt++)
                #pragma unroll
                for (int nt = 0; nt < 8; nt++)
                    mma_f16(C[mt][nt], a[mt], b[nt]);
        }
        // next iteration's post-WAIT barrier orders compute(i) before load(i+4)
    }

    // ---- epilogue: scatter C to out[b][n][e] ----
    #pragma unroll
    for (int mt = 0; mt < 4; mt++) {
        const int row0 = mtile * MT + (mbw + mt) * 16 + g;
        #pragma unroll
        for (int nt = 0; nt < 8; nt++) {
            const int col = ntile * NTI + (nbw + nt) * 8 + tg * 2;  // even
            const int bb = col >> 6;
            const int e = col & 63;
            float* p = out + ((size_t)bb * N_ + row0) * D_ + e;
            *reinterpret_cast<float2*>(p) = make_float2(C[mt][nt][0], C[mt][nt][1]);
            *reinterpret_cast<float2*>(p + 8 * D_) = make_float2(C[mt][nt][2], C[mt][nt][3]);
        }
    }
}

// ---------------------------------------------------------------------------
extern "C" void kernel_launch(void* const* d_in, const int* in_sizes, int n_in,
                              void* d_out, int out_size) {
    const float* Z = (const float*)d_in[0];   // [16, 4096, 64]
    const float* A = (const float*)d_in[1];   // [4096, 4096]
    const float* W = (const float*)d_in[2];   // [64, 64]
    float* out = (float*)d_out;               // [16, 4096, 64]

    aprep_kernel<<<2097152 / 256, 256>>>(A);
    zw_kernel<<<dim3(N_ / 64, B_), 256>>>(Z, W);

    cudaFuncSetAttribute(gemm_mma_kernel,
                         cudaFuncAttributeMaxDynamicSharedMemorySize, SMEM_BYTES);
    gemm_mma_kernel<<<dim3(NCOL / NTI, N_ / MT), 256, SMEM_BYTES>>>(out);
}